// round 9
// baseline (speedup 1.0000x reference)
#include <cuda_runtime.h>

#define B_      16
#define CL_     512
#define N_      3136
#define NV_     (N_ / 4)        // 784 float4 per row
#define V4T     28              // float4 columns per tile: 784 = 28 * 28
#define TILES_R 28
#define TPB_R   448             // 16 c-groups x 28 lanes
#define NGRP    16
#define CSUB    (CL_ / NGRP)    // 32 c per group
#define NPART   (B_ * TILES_R)  // 448 t-partials total

// Scratch (__device__ globals — allocation-free rule)
__device__ float4       d_g4[B_ * NV_];   // final g (~200 KB)
__device__ float        d_part[NPART];    // per-(b,tile) partial sums of t
__device__ float        d_mt[B_];         // mean(t) per batch
__device__ unsigned int d_ctr;            // completion ticket (self-resetting)

// Pass 1: grid (28, 16) x 448 threads. Block = (n-tile of 28 float4, b), ALL c.
// Writes final g directly. Last-finishing block folds the 448 t-partials into d_mt.
__global__ __launch_bounds__(TPB_R) void reduce_kernel(
    const float* __restrict__ x,
    const float* __restrict__ theta_w,
    const float* __restrict__ g_w)
{
    __shared__ float  s_tw[CL_];
    __shared__ float  s_gw[CL_];
    __shared__ float4 s_g[TPB_R];
    __shared__ float  s_warp[TPB_R / 32];
    __shared__ unsigned int s_ticket;

    const int tile = blockIdx.x;
    const int b    = blockIdx.y;
    const int gr   = threadIdx.x / V4T;          // 0..15
    const int ln   = threadIdx.x % V4T;          // 0..27
    const int n4   = tile * V4T + ln;            // < 784 always

    for (int c = threadIdx.x; c < CL_; c += TPB_R) {
        s_tw[c] = theta_w[c];
        s_gw[c] = g_w[c];
    }
    __syncthreads();

    const float4* x4 = reinterpret_cast<const float4*>(x) + (size_t)b * CL_ * NV_;

    float  t  = 0.0f;
    float4 g4 = make_float4(0.f, 0.f, 0.f, 0.f);

    {
        const int cl0 = gr * CSUB;
        const float4* xp = x4 + (size_t)cl0 * NV_ + n4;
        #pragma unroll 8
        for (int c = 0; c < CSUB; c++) {
            float4 v  = __ldg(xp + (size_t)c * NV_);
            float  tw = s_tw[cl0 + c];
            float  gw = s_gw[cl0 + c];
            t = fmaf((v.x + v.y) + (v.z + v.w), tw, t);
            g4.x = fmaf(v.x, gw, g4.x);
            g4.y = fmaf(v.y, gw, g4.y);
            g4.z = fmaf(v.z, gw, g4.z);
            g4.w = fmaf(v.w, gw, g4.w);
        }
    }

    // combine g across the 16 intra-block c-groups -> final g
    s_g[threadIdx.x] = g4;
    __syncthreads();
    if (threadIdx.x < V4T) {
        float4 acc = s_g[threadIdx.x];
        #pragma unroll
        for (int g = 1; g < NGRP; g++) {
            float4 p = s_g[threadIdx.x + g * V4T];
            acc.x += p.x; acc.y += p.y; acc.z += p.z; acc.w += p.w;
        }
        d_g4[b * NV_ + n4] = acc;
    }

    // reduce t across the block -> one partial
    #pragma unroll
    for (int off = 16; off > 0; off >>= 1)
        t += __shfl_down_sync(0xFFFFFFFFu, t, off);
    if ((threadIdx.x & 31) == 0) s_warp[threadIdx.x >> 5] = t;
    __syncthreads();
    if (threadIdx.x == 0) {
        float s = 0.0f;
        #pragma unroll
        for (int w = 0; w < TPB_R / 32; w++) s += s_warp[w];
        d_part[b * TILES_R + tile] = s;
    }

    // ---- last-block fold of t-partials into d_mt (deterministic values) ----
    __threadfence();                       // make d_part write visible (release)
    if (threadIdx.x == 0)
        s_ticket = atomicAdd(&d_ctr, 1u);
    __syncthreads();
    if (s_ticket == (unsigned int)(gridDim.x * gridDim.y - 1)) {
        if (threadIdx.x < B_) {
            float s = 0.0f;
            #pragma unroll
            for (int k = 0; k < TILES_R; k++) s += d_part[threadIdx.x * TILES_R + k];
            d_mt[threadIdx.x] = s * (1.0f / (float)N_);
        }
        if (threadIdx.x == 0) d_ctr = 0;   // self-reset for next graph replay
        __threadfence();
    }
}

// Pass 2: 2 loads + 1 store per thread. Reverse traversal so first reads hit the
// L2-resident tail of x from pass 1.
__global__ __launch_bounds__(256) void out_kernel(
    const float* __restrict__ x,
    const float* __restrict__ h_w,
    const float* __restrict__ h_b,
    float* __restrict__ out)
{
    const int total = B_ * CL_ * NV_;                      // 6,422,528 vec4
    const int v = total - 1 - (blockIdx.x * blockDim.x + threadIdx.x);

    const int n4  = v % NV_;
    const int row = v / NV_;          // row = b*CL + c
    const int c   = row % CL_;
    const int b   = row / CL_;

    const float mt  = __ldg(&d_mt[b]);      // uniform per block -> L1 hit
    const float hwc = h_w[c] * mt;
    const float hbc = h_b[c];

    const float4 g4 = d_g4[b * NV_ + n4];
    const float4 x4 = __ldcs(reinterpret_cast<const float4*>(x) + v);   // last use of x

    float4 o;
    o.x = fmaf(g4.x, hwc, x4.x) + hbc;
    o.y = fmaf(g4.y, hwc, x4.y) + hbc;
    o.z = fmaf(g4.z, hwc, x4.z) + hbc;
    o.w = fmaf(g4.w, hwc, x4.w) + hbc;

    __stcs(reinterpret_cast<float4*>(out) + v, o);          // streaming store
}

extern "C" void kernel_launch(void* const* d_in, const int* in_sizes, int n_in,
                              void* d_out, int out_size)
{
    const float* x       = (const float*)d_in[0];
    const float* theta_w = (const float*)d_in[1];
    const float* g_w     = (const float*)d_in[2];
    const float* h_w     = (const float*)d_in[3];
    const float* h_b     = (const float*)d_in[4];
    float*       out     = (float*)d_out;

    dim3 grid1(TILES_R, B_);               // 28 x 16 = 448 blocks, 448 threads
    reduce_kernel<<<grid1, TPB_R>>>(x, theta_w, g_w);

    const int total_vec4 = B_ * CL_ * NV_; // 6,422,528
    out_kernel<<<total_vec4 / 256, 256>>>(x, h_w, h_b, out);
}